// round 6
// baseline (speedup 1.0000x reference)
#include <cuda_runtime.h>
#include <cuda_bf16.h>
#include <cuda_fp16.h>
#include <cstdint>

#define NQ 16384
#define NK 16384
#define DIM 256
#define DV 256

// ---------------- scratch (static device arrays; no allocations) ----------------
__device__ __nv_bfloat16 g_Qh[NQ * DIM];
__device__ __nv_bfloat16 g_Ql[NQ * DIM];
__device__ __nv_bfloat16 g_Kh[NK * DIM];
__device__ __nv_bfloat16 g_Kl[NK * DIM];
__device__ __half g_Vf[NK * DV];
__device__ __half g_Wf[(size_t)NQ * NK];  // fp16 copy of normalized weights (512 MB)

// ---------------- helpers ----------------
__device__ __forceinline__ unsigned smem_u32(const void* p) {
    return (unsigned)__cvta_generic_to_shared(p);
}
__device__ __forceinline__ void cp16(void* dst, const void* src) {
    unsigned d = smem_u32(dst);
    asm volatile("cp.async.cg.shared.global [%0], [%1], 16;" :: "r"(d), "l"(src));
}
__device__ __forceinline__ void cp_commit() {
    asm volatile("cp.async.commit_group;");
}
template <int N>
__device__ __forceinline__ void cp_wait() {
    asm volatile("cp.async.wait_group %0;" :: "n"(N));
}
__device__ __forceinline__ void ldsm_x4(uint32_t* r, unsigned addr) {
    asm volatile("ldmatrix.sync.aligned.m8n8.x4.shared.b16 {%0,%1,%2,%3}, [%4];"
                 : "=r"(r[0]), "=r"(r[1]), "=r"(r[2]), "=r"(r[3]) : "r"(addr));
}
__device__ __forceinline__ void ldsm_x2(uint32_t* r, unsigned addr) {
    asm volatile("ldmatrix.sync.aligned.m8n8.x2.shared.b16 {%0,%1}, [%2];"
                 : "=r"(r[0]), "=r"(r[1]) : "r"(addr));
}
__device__ __forceinline__ void ldsm_x2_trans(uint32_t* r, unsigned addr) {
    asm volatile("ldmatrix.sync.aligned.m8n8.x2.trans.shared.b16 {%0,%1}, [%2];"
                 : "=r"(r[0]), "=r"(r[1]) : "r"(addr));
}
__device__ __forceinline__ void mma_bf16(float* c, const uint32_t* a, const uint32_t* b) {
    asm volatile(
        "mma.sync.aligned.m16n8k16.row.col.f32.bf16.bf16.f32 "
        "{%0,%1,%2,%3},{%4,%5,%6,%7},{%8,%9},{%0,%1,%2,%3};"
        : "+f"(c[0]), "+f"(c[1]), "+f"(c[2]), "+f"(c[3])
        : "r"(a[0]), "r"(a[1]), "r"(a[2]), "r"(a[3]), "r"(b[0]), "r"(b[1]));
}
__device__ __forceinline__ void mma_fp16(float* c, const uint32_t* a, const uint32_t* b) {
    asm volatile(
        "mma.sync.aligned.m16n8k16.row.col.f32.f16.f16.f32 "
        "{%0,%1,%2,%3},{%4,%5,%6,%7},{%8,%9},{%0,%1,%2,%3};"
        : "+f"(c[0]), "+f"(c[1]), "+f"(c[2]), "+f"(c[3])
        : "r"(a[0]), "r"(a[1]), "r"(a[2]), "r"(a[3]), "r"(b[0]), "r"(b[1]));
}

// ---------------- kernel 1: splits (Q,K -> bf16 hi/lo; V -> fp16) ----------------
__global__ void split_all_kernel(const float* __restrict__ Q,
                                 const float* __restrict__ K,
                                 const float* __restrict__ V) {
    int i = blockIdx.x * blockDim.x + threadIdx.x;
    if (i < NQ * DIM) {
        float q = Q[i];
        __nv_bfloat16 qh = __float2bfloat16(q);
        g_Qh[i] = qh;
        g_Ql[i] = __float2bfloat16(q - __bfloat162float(qh));
        float k = K[i];
        __nv_bfloat16 kh = __float2bfloat16(k);
        g_Kh[i] = kh;
        g_Kl[i] = __float2bfloat16(k - __bfloat162float(kh));
        g_Vf[i] = __float2half_rn(V[i]);
    }
}

// ---------------- kernel 2: S = Q K^T (raw scores), cp.async double-buffered ----------------
// CTA tile 128x128, 512 threads, 16 warps 4(m)x4(n), warp tile 32x32.
// S = Qh*Kh + Qh*Kl + Ql*Kh (error-compensated bf16).
#define QKS 72
#define QK_A (128 * QKS)

__global__ __launch_bounds__(512, 1) void qk_kernel(float* __restrict__ W) {
    extern __shared__ __nv_bfloat16 sm[];

    const int tid = threadIdx.x;
    const int lane = tid & 31, w = tid >> 5;
    const int wm = w >> 2, wn = w & 3;
    const int qBase = blockIdx.y * 128;
    const int kBase = blockIdx.x * 128;

    float acc[2][4][4];
#pragma unroll
    for (int mi = 0; mi < 2; mi++)
#pragma unroll
        for (int ni = 0; ni < 4; ni++)
#pragma unroll
            for (int j = 0; j < 4; j++) acc[mi][ni][j] = 0.f;

    auto load_stage = [&](int s, int kc) {
        __nv_bfloat16* b0 = sm + s * 4 * QK_A;
#pragma unroll
        for (int it = 0; it < 2; it++) {
            int idx = it * 512 + tid;
            int row = idx >> 3, cv = (idx & 7) << 3;
            size_t gq = (size_t)(qBase + row) * DIM + kc + cv;
            size_t gk = (size_t)(kBase + row) * DIM + kc + cv;
            cp16(b0 + row * QKS + cv, g_Qh + gq);
            cp16(b0 + QK_A + row * QKS + cv, g_Ql + gq);
            cp16(b0 + 2 * QK_A + row * QKS + cv, g_Kh + gk);
            cp16(b0 + 3 * QK_A + row * QKS + cv, g_Kl + gk);
        }
        cp_commit();
    };

    load_stage(0, 0);
    for (int ci = 0; ci < 4; ci++) {
        if (ci < 3) {
            load_stage((ci + 1) & 1, (ci + 1) * 64);
            cp_wait<1>();
        } else {
            cp_wait<0>();
        }
        __syncthreads();

        const __nv_bfloat16* sQh = sm + (ci & 1) * 4 * QK_A;
        const __nv_bfloat16* sQl = sQh + QK_A;
        const __nv_bfloat16* sKh = sQh + 2 * QK_A;
        const __nv_bfloat16* sKl = sQh + 3 * QK_A;

#pragma unroll
        for (int ks = 0; ks < 4; ks++) {
            const int k0 = ks * 16;
            uint32_t ah[2][4], al[2][4], bh[4][2], bl[4][2];
#pragma unroll
            for (int mi = 0; mi < 2; mi++) {
                int m0 = wm * 32 + mi * 16;
                int mat = lane >> 3;
                int r = m0 + ((mat & 1) << 3) + (lane & 7);
                int c = k0 + ((mat >> 1) << 3);
                ldsm_x4(ah[mi], smem_u32(&sQh[r * QKS + c]));
                ldsm_x4(al[mi], smem_u32(&sQl[r * QKS + c]));
            }
#pragma unroll
            for (int ni = 0; ni < 4; ni++) {
                int n0 = wn * 32 + ni * 8;
                int mat = (lane >> 3) & 1;
                int r = n0 + (lane & 7);
                int c = k0 + (mat << 3);
                ldsm_x2(bh[ni], smem_u32(&sKh[r * QKS + c]));
                ldsm_x2(bl[ni], smem_u32(&sKl[r * QKS + c]));
            }
#pragma unroll
            for (int mi = 0; mi < 2; mi++)
#pragma unroll
                for (int ni = 0; ni < 4; ni++) {
                    mma_bf16(acc[mi][ni], ah[mi], bh[ni]);
                    mma_bf16(acc[mi][ni], ah[mi], bl[ni]);
                    mma_bf16(acc[mi][ni], al[mi], bh[ni]);
                }
        }
        __syncthreads();
    }

#pragma unroll
    for (int mi = 0; mi < 2; mi++) {
        int r0 = qBase + wm * 32 + mi * 16 + (lane >> 2);
#pragma unroll
        for (int ni = 0; ni < 4; ni++) {
            int c0 = kBase + wn * 32 + ni * 8 + ((lane & 3) << 1);
            *(float2*)&W[(size_t)r0 * NK + c0] = make_float2(acc[mi][ni][0], acc[mi][ni][1]);
            *(float2*)&W[(size_t)(r0 + 8) * NK + c0] = make_float2(acc[mi][ni][2], acc[mi][ni][3]);
        }
    }
}

// ---------------- kernel 3: in-place row softmax on W + fp16 copy to g_Wf ----------------
__global__ __launch_bounds__(256, 1) void softmax_kernel(float* __restrict__ W) {
    extern __shared__ float rowbuf[];
    __shared__ float red[8];
    const int tid = threadIdx.x;
    const int lane = tid & 31, w = tid >> 5;
    float4* Wr = (float4*)(W + (size_t)blockIdx.x * NK);
    __half2* Wf2 = (__half2*)(g_Wf + (size_t)blockIdx.x * NK);
    float4* R = (float4*)rowbuf;

    float lmax = -3.0e38f;
#pragma unroll
    for (int i = 0; i < 16; i++) {
        int idx = i * 256 + tid;
        float4 t = Wr[idx];
        R[idx] = t;
        lmax = fmaxf(lmax, fmaxf(fmaxf(t.x, t.y), fmaxf(t.z, t.w)));
    }
#pragma unroll
    for (int o = 16; o; o >>= 1) lmax = fmaxf(lmax, __shfl_xor_sync(0xffffffffu, lmax, o));
    if (lane == 0) red[w] = lmax;
    __syncthreads();
    float mx = red[0];
#pragma unroll
    for (int j = 1; j < 8; j++) mx = fmaxf(mx, red[j]);
    __syncthreads();

    float lsum = 0.f;
#pragma unroll
    for (int i = 0; i < 16; i++) {
        int idx = i * 256 + tid;
        float4 t = R[idx];
        t.x = __expf(t.x - mx);
        t.y = __expf(t.y - mx);
        t.z = __expf(t.z - mx);
        t.w = __expf(t.w - mx);
        R[idx] = t;
        lsum += t.x + t.y + t.z + t.w;
    }
#pragma unroll
    for (int o = 16; o; o >>= 1) lsum += __shfl_xor_sync(0xffffffffu, lsum, o);
    if (lane == 0) red[w] = lsum;
    __syncthreads();
    float total = 0.f;
#pragma unroll
    for (int j = 0; j < 8; j++) total += red[j];
    float inv = 1.0f / total;

#pragma unroll
    for (int i = 0; i < 16; i++) {
        int idx = i * 256 + tid;
        float4 t = R[idx];
        t.x *= inv; t.y *= inv; t.z *= inv; t.w *= inv;
        Wr[idx] = t;
        Wf2[idx * 2] = __floats2half2_rn(t.x, t.y);
        Wf2[idx * 2 + 1] = __floats2half2_rn(t.z, t.w);
    }
}

// ---------------- kernel 4: X = W V, fp16 single pass, W+V both cp.async ----------------
// CTA tile 64(m) x 256(n); K-chunks of 64; 2 CTAs/SM.
#define PWS 72
#define PVS 264

__global__ __launch_bounds__(256, 2) void pv_kernel(float* __restrict__ X) {
    extern __shared__ __half smh[];
    __half* sW = smh;                   // 2 stages x 64 x 72
    __half* sV = smh + 2 * 64 * PWS;    // 2 stages x 64 x 264

    const int tid = threadIdx.x;
    const int lane = tid & 31, w = tid >> 5;
    const int wm = w >> 2, wn = w & 3;
    const int mBase = blockIdx.x * 64;

    float acc[2][8][4];
#pragma unroll
    for (int mi = 0; mi < 2; mi++)
#pragma unroll
        for (int ni = 0; ni < 8; ni++)
#pragma unroll
            for (int j = 0; j < 4; j++) acc[mi][ni][j] = 0.f;

    auto load_stage = [&](int s, int k0) {
        __half* wf = sW + s * 64 * PWS;
        __half* vf = sV + s * 64 * PVS;
#pragma unroll
        for (int it = 0; it < 2; it++) {
            int idx = it * 256 + tid;
            int row = idx >> 3, cv = (idx & 7) << 3;
            cp16(wf + row * PWS + cv, g_Wf + (size_t)(mBase + row) * NK + k0 + cv);
        }
#pragma unroll
        for (int it = 0; it < 8; it++) {
            int idx = it * 256 + tid;
            int row = idx >> 5, cv = (idx & 31) << 3;
            cp16(vf + row * PVS + cv, g_Vf + (size_t)(k0 + row) * DV + cv);
        }
        cp_commit();
    };

    load_stage(0, 0);

    for (int i = 0; i < NK / 64; i++) {
        if (i < NK / 64 - 1) {
            load_stage((i + 1) & 1, (i + 1) * 64);
            cp_wait<1>();
        } else {
            cp_wait<0>();
        }
        __syncthreads();

        const __half* wf = sW + (i & 1) * 64 * PWS;
        const __half* vf = sV + (i & 1) * 64 * PVS;

#pragma unroll
        for (int ks = 0; ks < 4; ks++) {
            int kk = ks * 16;
            uint32_t a[2][4], b[8][2];
#pragma unroll
            for (int mi = 0; mi < 2; mi++) {
                int m0 = wm * 32 + mi * 16;
                int mat = lane >> 3;
                int r = m0 + ((mat & 1) << 3) + (lane & 7);
                int c = kk + ((mat >> 1) << 3);
                ldsm_x4(a[mi], smem_u32(&wf[r * PWS + c]));
            }
#pragma unroll
            for (int ni = 0; ni < 8; ni++) {
                int n0 = wn * 64 + ni * 8;
                int mat = (lane >> 3) & 1;
                int r = kk + (mat << 3) + (lane & 7);
                ldsm_x2_trans(b[ni], smem_u32(&vf[r * PVS + n0]));
            }
#pragma unroll
            for (int mi = 0; mi < 2; mi++)
#pragma unroll
                for (int ni = 0; ni < 8; ni++)
                    mma_fp16(acc[mi][ni], a[mi], b[ni]);
        }
        __syncthreads();
    }

#pragma unroll
    for (int mi = 0; mi < 2; mi++) {
        int r0 = mBase + wm * 32 + mi * 16 + (lane >> 2);
#pragma unroll
        for (int ni = 0; ni < 8; ni++) {
            int c0 = wn * 64 + ni * 8 + ((lane & 3) << 1);
            *(float2*)&X[(size_t)r0 * DV + c0] = make_float2(acc[mi][ni][0], acc[mi][ni][1]);
            *(float2*)&X[(size_t)(r0 + 8) * DV + c0] = make_float2(acc[mi][ni][2], acc[mi][ni][3]);
        }
    }
}

// ---------------- launcher ----------------
extern "C" void kernel_launch(void* const* d_in, const int* in_sizes, int n_in,
                              void* d_out, int out_size) {
    const float* Q = (const float*)d_in[0];
    const float* K = (const float*)d_in[1];
    const float* V = (const float*)d_in[2];
    float* X = (float*)d_out;                    // [NQ, DV]
    float* W = (float*)d_out + (size_t)NQ * DV;  // [NQ, NK]

    const int qk_smem = 2 * 4 * QK_A * 2;                       // 147456 B
    const int sm_smem = NK * 4;                                 // 65536 B
    const int pv_smem = (2 * 64 * PWS + 2 * 64 * PVS) * 2;      // 86016 B
    cudaFuncSetAttribute(qk_kernel, cudaFuncAttributeMaxDynamicSharedMemorySize, qk_smem);
    cudaFuncSetAttribute(softmax_kernel, cudaFuncAttributeMaxDynamicSharedMemorySize, sm_smem);
    cudaFuncSetAttribute(pv_kernel, cudaFuncAttributeMaxDynamicSharedMemorySize, pv_smem);

    split_all_kernel<<<(NQ * DIM + 255) / 256, 256>>>(Q, K, V);

    dim3 qkGrid(NK / 128, NQ / 128);
    qk_kernel<<<qkGrid, 512, qk_smem>>>(W);

    softmax_kernel<<<NQ, 256, sm_smem>>>(W);

    pv_kernel<<<NQ / 64, 256, pv_smem>>>(X);
}